// round 16
// baseline (speedup 1.0000x reference)
#include <cuda_runtime.h>
#include <cstdint>

#define N_NODES 100000
#define N_EDGES 1000000
#define DIM 64
#define BN_EPS 1e-5f
#define CAP 96                                          // max in-degree bucket

#define GEMM_BM 128                                     // nodes per block
#define GEMM_NBLK ((N_NODES + GEMM_BM - 1) / GEMM_BM)   // 782
// dynamic smem: duplicated A tile (u64) + transposed W (float)
#define SMEM_GEMM (GEMM_BM * DIM * 8 + DIM * DIM * 4)   // 65536 + 16384 = 80KB

typedef unsigned long long u64;

// packed fp32x2 FMA (sm_103a): d = a*b + c on both 32-bit halves
#define FMA2(d, a, b, c) \
    asm("fma.rn.f32x2 %0, %1, %2, %3;" : "=l"(d) : "l"(a), "l"(b), "l"(c))
#define PACK_DUP(d, s) \
    asm("mov.b64 %0, {%1, %1};" : "=l"(d) : "r"(s))
#define UNPACK2(lo, hi, in) \
    asm("mov.b64 {%0, %1}, %2;" : "=r"(lo), "=r"(hi) : "l"(in))

// ---------------- scratch (static device globals; BSS -> zero at load) ------
__device__ int   g_cnt[N_NODES];                 // in-degree counters
__device__ int   g_bucket[(size_t)N_NODES * CAP];// per-dst neighbor lists
__device__ float g_aggr[(size_t)N_NODES * DIM];  // mean-aggregated features
__device__ float g_out[(size_t)N_NODES * DIM];   // post-linear output
__device__ float g_bnstats[2 * DIM];             // [0:64) sum, [64:128) sumsq

// ---------------- kernel 1: fused histogram + bucket scatter (int4 edges) ---
__global__ void k_scatter(const int* __restrict__ ei) {
    int t = blockIdx.x * blockDim.x + threadIdx.x;
    if (blockIdx.x == 0 && threadIdx.x < 2 * DIM) g_bnstats[threadIdx.x] = 0.0f;
    int e = t * 4;
    if (e < N_EDGES) {                               // N_EDGES % 4 == 0
        int4 s = *reinterpret_cast<const int4*>(ei + e);
        int4 d = *reinterpret_cast<const int4*>(ei + N_EDGES + e);
        int p;
        p = atomicAdd(&g_cnt[d.x], 1); if (p < CAP) g_bucket[(size_t)d.x * CAP + p] = s.x;
        p = atomicAdd(&g_cnt[d.y], 1); if (p < CAP) g_bucket[(size_t)d.y * CAP + p] = s.y;
        p = atomicAdd(&g_cnt[d.z], 1); if (p < CAP) g_bucket[(size_t)d.z * CAP + p] = s.z;
        p = atomicAdd(&g_cnt[d.w], 1); if (p < CAP) g_bucket[(size_t)d.w * CAP + p] = s.w;
    }
#if __CUDA_ARCH__ >= 900
    cudaTriggerProgrammaticLaunchCompletion();
#endif
}

// ---------------- kernel 2: dst-major aggregation (PDL secondary) -----------
__global__ void k_aggr(const float4* __restrict__ x4) {
    int g    = blockIdx.x * (blockDim.x >> 4) + (threadIdx.x >> 4);
    int lane = threadIdx.x & 15;
    const float4* xl = x4 + lane;
    float4 acc = make_float4(0.f, 0.f, 0.f, 0.f);
    bool act = (g < N_NODES);
    if (act) acc = __ldg(xl + g * (DIM / 4));        // self loop (input only)
#if __CUDA_ARCH__ >= 900
    cudaGridDependencySynchronize();                 // wait: g_cnt/g_bucket
#endif
    if (!act) return;
    int cnt = __ldg(g_cnt + g);
    if (cnt > CAP) cnt = CAP;                        // safety clamp
    const int* bp = g_bucket + (size_t)g * CAP;
    int i = 0;
    for (; i + 4 <= cnt; i += 4) {
        int4 s = *reinterpret_cast<const int4*>(bp + i);
        float4 v0 = __ldg(xl + s.x * (DIM / 4));
        float4 v1 = __ldg(xl + s.y * (DIM / 4));
        float4 v2 = __ldg(xl + s.z * (DIM / 4));
        float4 v3 = __ldg(xl + s.w * (DIM / 4));
        acc.x += (v0.x + v1.x) + (v2.x + v3.x);
        acc.y += (v0.y + v1.y) + (v2.y + v3.y);
        acc.z += (v0.z + v1.z) + (v2.z + v3.z);
        acc.w += (v0.w + v1.w) + (v2.w + v3.w);
    }
    for (; i < cnt; i++) {
        float4 v = __ldg(xl + __ldg(bp + i) * (DIM / 4));
        acc.x += v.x; acc.y += v.y; acc.z += v.z; acc.w += v.w;
    }
    float inv = 1.0f / (float)(cnt + 1);
    acc.x *= inv; acc.y *= inv; acc.z *= inv; acc.w *= inv;
    reinterpret_cast<float4*>(g_aggr)[g * (DIM / 4) + lane] = acc;
#if __CUDA_ARCH__ >= 900
    cudaTriggerProgrammaticLaunchCompletion();
#endif
}

// ---------------- kernel 3: f32x2 GEMM, duplicated-A smem (PDL secondary) ---
// A tile stored as u64 (val,val) pairs -> inner loop is 1 LDS.64 + 2 FMA2
// per (k, node): no dup-MOVs, half the a-load instructions.
__global__ void __launch_bounds__(256) k_gemm(const float* __restrict__ w,
                                              const float* __restrict__ b) {
    extern __shared__ u64 dsm[];
    u64*   sAd = dsm;                                    // [GEMM_BM*DIM] u64
    float* sW  = reinterpret_cast<float*>(dsm + GEMM_BM * DIM); // [DIM*DIM]

    int tid = threadIdx.x;
    int tx = tid & 15;          // channel quad
    int ty = tid >> 4;          // node octet
    int n0 = blockIdx.x * GEMM_BM;

    for (int idx = tid; idx < DIM * DIM; idx += 256) {   // input-only: pre-sync
        int j = idx >> 6, k = idx & 63;
        sW[k * DIM + j] = w[idx];
    }
    float4 bv = *reinterpret_cast<const float4*>(&b[tx * 4]);  // input-only

#if __CUDA_ARCH__ >= 900
    cudaGridDependencySynchronize();                 // wait: g_aggr
#endif

    // stage A duplicated: each float -> (val,val) u64
    for (int idx = tid; idx < GEMM_BM * (DIM / 4); idx += 256) {
        int row = idx >> 4, q = idx & 15;
        int n = n0 + row;
        float4 v = (n < N_NODES)
            ? reinterpret_cast<const float4*>(g_aggr)[n * (DIM / 4) + q]
            : make_float4(0.f, 0.f, 0.f, 0.f);
        u64 d0, d1, d2, d3;
        PACK_DUP(d0, __float_as_uint(v.x));
        PACK_DUP(d1, __float_as_uint(v.y));
        PACK_DUP(d2, __float_as_uint(v.z));
        PACK_DUP(d3, __float_as_uint(v.w));
        u64* dst = &sAd[row * DIM + q * 4];
        dst[0] = d0; dst[1] = d1; dst[2] = d2; dst[3] = d3;
    }
    __syncthreads();

    u64 acc01[8], acc23[8];
    #pragma unroll
    for (int i = 0; i < 8; i++) { acc01[i] = 0ULL; acc23[i] = 0ULL; }

    #pragma unroll 4
    for (int k = 0; k < DIM; k++) {
        double2 wp = *reinterpret_cast<const double2*>(&sW[k * DIM + tx * 4]);
        u64 w01 = __double_as_longlong(wp.x);
        u64 w23 = __double_as_longlong(wp.y);
        #pragma unroll
        for (int i = 0; i < 8; i++) {
            u64 aa = sAd[(ty * 8 + i) * DIM + k];    // pre-duplicated
            FMA2(acc01[i], aa, w01, acc01[i]);
            FMA2(acc23[i], aa, w23, acc23[i]);
        }
    }

    float psum[4] = {0, 0, 0, 0};
    float psq[4]  = {0, 0, 0, 0};

    #pragma unroll
    for (int i = 0; i < 8; i++) {
        int n = n0 + ty * 8 + i;
        if (n < N_NODES) {
            unsigned r0, r1, r2, r3;
            UNPACK2(r0, r1, acc01[i]);
            UNPACK2(r2, r3, acc23[i]);
            float4 o;
            o.x = __uint_as_float(r0) + bv.x;
            o.y = __uint_as_float(r1) + bv.y;
            o.z = __uint_as_float(r2) + bv.z;
            o.w = __uint_as_float(r3) + bv.w;
            reinterpret_cast<float4*>(g_out)[n * (DIM / 4) + tx] = o;
            psum[0] += o.x; psum[1] += o.y; psum[2] += o.z; psum[3] += o.w;
            psq[0] += o.x * o.x; psq[1] += o.y * o.y;
            psq[2] += o.z * o.z; psq[3] += o.w * o.w;
        }
    }

    __syncthreads();
    float (*sRed)[DIM] = reinterpret_cast<float (*)[DIM]>(sAd);

    #pragma unroll
    for (int c = 0; c < 4; c++) sRed[ty][tx * 4 + c] = psum[c];
    __syncthreads();
    #pragma unroll
    for (int st = 8; st > 0; st >>= 1) {
        if (ty < st)
            #pragma unroll
            for (int c = 0; c < 4; c++)
                sRed[ty][tx * 4 + c] += sRed[ty + st][tx * 4 + c];
        __syncthreads();
    }
    if (ty == 0)
        #pragma unroll
        for (int c = 0; c < 4; c++)
            atomicAdd(&g_bnstats[tx * 4 + c], sRed[0][tx * 4 + c]);
    __syncthreads();

    #pragma unroll
    for (int c = 0; c < 4; c++) sRed[ty][tx * 4 + c] = psq[c];
    __syncthreads();
    #pragma unroll
    for (int st = 8; st > 0; st >>= 1) {
        if (ty < st)
            #pragma unroll
            for (int c = 0; c < 4; c++)
                sRed[ty][tx * 4 + c] += sRed[ty + st][tx * 4 + c];
        __syncthreads();
    }
    if (ty == 0)
        #pragma unroll
        for (int c = 0; c < 4; c++)
            atomicAdd(&g_bnstats[DIM + tx * 4 + c], sRed[0][tx * 4 + c]);
#if __CUDA_ARCH__ >= 900
    cudaTriggerProgrammaticLaunchCompletion();
#endif
}

// ---------------- kernel 4: BN finalize + residual + relu (PDL secondary) ---
__global__ void k_final(const float4* __restrict__ x4,
                        const float4* __restrict__ gamma4,
                        const float4* __restrict__ beta4,
                        float4* __restrict__ out4) {
    int i = blockIdx.x * blockDim.x + threadIdx.x;
    int q = i & 15;
    bool act = (i < N_NODES * (DIM / 4));
    float4 xv = make_float4(0.f, 0.f, 0.f, 0.f);
    float4 gm = make_float4(0.f, 0.f, 0.f, 0.f);
    float4 bt = make_float4(0.f, 0.f, 0.f, 0.f);
    if (act) {
        xv = __ldg(x4 + i);
        gm = __ldg(gamma4 + q);
        bt = __ldg(beta4 + q);
    }
#if __CUDA_ARCH__ >= 900
    cudaGridDependencySynchronize();                 // wait: g_bnstats/g_out
#endif
    if (i < N_NODES) g_cnt[i] = 0;                   // reset for next launch
    if (!act) return;
    const float invN = 1.0f / (float)N_NODES;

    float4 s  = *reinterpret_cast<const float4*>(&g_bnstats[q * 4]);
    float4 sq = *reinterpret_cast<const float4*>(&g_bnstats[DIM + q * 4]);

    float m0 = s.x * invN, m1 = s.y * invN, m2 = s.z * invN, m3 = s.w * invN;
    float sc0 = gm.x * rsqrtf(sq.x * invN - m0 * m0 + BN_EPS);
    float sc1 = gm.y * rsqrtf(sq.y * invN - m1 * m1 + BN_EPS);
    float sc2 = gm.z * rsqrtf(sq.z * invN - m2 * m2 + BN_EPS);
    float sc3 = gm.w * rsqrtf(sq.w * invN - m3 * m3 + BN_EPS);
    float sh0 = bt.x - m0 * sc0;
    float sh1 = bt.y - m1 * sc1;
    float sh2 = bt.z - m2 * sc2;
    float sh3 = bt.w - m3 * sc3;

    float4 o = reinterpret_cast<const float4*>(g_out)[i];
    float4 r;
    r.x = fmaxf(fmaf(o.x, sc0, sh0) + xv.x, 0.0f);
    r.y = fmaxf(fmaf(o.y, sc1, sh1) + xv.y, 0.0f);
    r.z = fmaxf(fmaf(o.z, sc2, sh2) + xv.z, 0.0f);
    r.w = fmaxf(fmaf(o.w, sc3, sh3) + xv.w, 0.0f);
    out4[i] = r;
}

// ---------------- launch: PDL chain ------------------------------------------
template <typename... Args>
static void launch_pdl(void (*kern)(Args...), int grid, int block, bool pdl,
                       unsigned smem, Args... args) {
    cudaLaunchConfig_t cfg = {};
    cfg.gridDim  = dim3(grid, 1, 1);
    cfg.blockDim = dim3(block, 1, 1);
    cfg.dynamicSmemBytes = smem;
    cudaLaunchAttribute attr[1];
    if (pdl) {
        attr[0].id = cudaLaunchAttributeProgrammaticStreamSerialization;
        attr[0].val.programmaticStreamSerializationAllowed = 1;
        cfg.attrs = attr;
        cfg.numAttrs = 1;
    }
    cudaLaunchKernelEx(&cfg, kern, args...);
}

extern "C" void kernel_launch(void* const* d_in, const int* in_sizes, int n_in,
                              void* d_out, int out_size) {
    const float* x     = (const float*)d_in[0];
    const int*   ei    = (const int*)d_in[1];
    const float* w     = (const float*)d_in[2];
    const float* b     = (const float*)d_in[3];
    const float* gamma = (const float*)d_in[4];
    const float* beta  = (const float*)d_in[5];
    float*       out   = (float*)d_out;

    const int vec = N_NODES * (DIM / 4);

    cudaFuncSetAttribute(k_gemm, cudaFuncAttributeMaxDynamicSharedMemorySize,
                         SMEM_GEMM);

    launch_pdl(k_scatter, (N_EDGES / 4 + 255) / 256, 256, false, 0u, ei);
    launch_pdl(k_aggr, (N_NODES * 16 + 255) / 256, 256, true, 0u,
               (const float4*)x);
    launch_pdl(k_gemm, GEMM_NBLK, 256, true, (unsigned)SMEM_GEMM, w, b);
    launch_pdl(k_final, (vec + 255) / 256, 256, true, 0u,
               (const float4*)x, (const float4*)gamma,
               (const float4*)beta, (float4*)out);
}

// round 17
// speedup vs baseline: 1.0960x; 1.0960x over previous
#include <cuda_runtime.h>
#include <cuda_fp16.h>
#include <cstdint>

#define N_NODES 100000
#define N_EDGES 1000000
#define DIM 64
#define BN_EPS 1e-5f
#define CAP 96                                          // max in-degree bucket

#define GEMM_BM 128                                     // nodes per block
#define GEMM_NBLK ((N_NODES + GEMM_BM - 1) / GEMM_BM)   // 782
#define SCAT_NT ((((N_EDGES + 255) / 256)) * 256)       // scatter thread count

typedef unsigned long long u64;

// packed fp32x2 FMA (sm_103a): d = a*b + c on both 32-bit halves
#define FMA2(d, a, b, c) \
    asm("fma.rn.f32x2 %0, %1, %2, %3;" : "=l"(d) : "l"(a), "l"(b), "l"(c))
#define PACK_DUP(d, s) \
    asm("mov.b64 %0, {%1, %1};" : "=l"(d) : "r"(s))
#define UNPACK2(lo, hi, in) \
    asm("mov.b64 {%0, %1}, %2;" : "=r"(lo), "=r"(hi) : "l"(in))

// ---------------- scratch (static device globals; BSS -> zero at load) ------
__device__ int    g_cnt[N_NODES];                  // in-degree counters
__device__ int    g_bucket[(size_t)N_NODES * CAP]; // per-dst neighbor lists
__device__ __half g_xh[(size_t)N_NODES * DIM];     // fp16 copy of x (gathers)
__device__ float  g_aggr[(size_t)N_NODES * DIM];   // mean-aggregated features
__device__ float  g_out[(size_t)N_NODES * DIM];    // post-linear output
__device__ float  g_bnstats[2 * DIM];              // [0:64) sum, [64:) sumsq

// unpack 4 halves (uint2) and accumulate into fp32 float4
__device__ __forceinline__ float4 acc_h4(float4 a, uint2 h) {
    __half2 p0 = *reinterpret_cast<__half2*>(&h.x);
    __half2 p1 = *reinterpret_cast<__half2*>(&h.y);
    float2 f0 = __half22float2(p0);
    float2 f1 = __half22float2(p1);
    a.x += f0.x; a.y += f0.y; a.z += f1.x; a.w += f1.y;
    return a;
}

// ---------------- kernel 1: scatter + fp16 conversion of x ------------------
__global__ void k_scatter(const int* __restrict__ ei,
                          const float2* __restrict__ x2) {
    int t = blockIdx.x * blockDim.x + threadIdx.x;
    if (blockIdx.x == 0 && threadIdx.x < 2 * DIM) g_bnstats[threadIdx.x] = 0.0f;
    // convert x -> fp16 copy (striped; overlaps the atomic scatter below)
    for (int i = t; i < N_NODES * DIM / 2; i += SCAT_NT) {
        float2 v = __ldg(x2 + i);
        reinterpret_cast<__half2*>(g_xh)[i] = __float22half2_rn(v);
    }
    if (t < N_EDGES) {
        int src = __ldg(ei + t);
        int dst = __ldg(ei + N_EDGES + t);
        int pos = atomicAdd(&g_cnt[dst], 1);
        if (pos < CAP) g_bucket[(size_t)dst * CAP + pos] = src;
    }
#if __CUDA_ARCH__ >= 900
    cudaTriggerProgrammaticLaunchCompletion();
#endif
}

// ---------------- kernel 2: dst-major aggregation, fp16 gathers -------------
// 16 lanes per node; lane owns channels [lane*4, lane*4+4): one uint2 (4
// halves) per gathered row -> half the L2 gather traffic vs fp32.
// Self-loop uses exact fp32 x; accumulation is fp32.
__global__ void k_aggr(const float4* __restrict__ x4) {
    int g    = blockIdx.x * (blockDim.x >> 4) + (threadIdx.x >> 4);
    int lane = threadIdx.x & 15;
    bool act = (g < N_NODES);
    float4 acc = make_float4(0.f, 0.f, 0.f, 0.f);
    if (act) acc = __ldg(x4 + g * (DIM / 4) + lane);   // self loop (input only)
#if __CUDA_ARCH__ >= 900
    cudaGridDependencySynchronize();                   // wait: cnt/bucket/xh
#endif
    if (!act) return;
    int cnt = __ldg(g_cnt + g);
    if (cnt > CAP) cnt = CAP;                          // safety clamp
    const int* bp = g_bucket + (size_t)g * CAP;
    const uint2* xh = reinterpret_cast<const uint2*>(g_xh) + lane; // +16/row
    int i = 0;
    for (; i + 4 <= cnt; i += 4) {
        int4 s = *reinterpret_cast<const int4*>(bp + i);
        uint2 h0 = __ldg(xh + s.x * 16);
        uint2 h1 = __ldg(xh + s.y * 16);
        uint2 h2 = __ldg(xh + s.z * 16);
        uint2 h3 = __ldg(xh + s.w * 16);
        acc = acc_h4(acc, h0);
        acc = acc_h4(acc, h1);
        acc = acc_h4(acc, h2);
        acc = acc_h4(acc, h3);
    }
    for (; i < cnt; i++) {
        uint2 h = __ldg(xh + __ldg(bp + i) * 16);
        acc = acc_h4(acc, h);
    }
    float inv = 1.0f / (float)(cnt + 1);
    acc.x *= inv; acc.y *= inv; acc.z *= inv; acc.w *= inv;
    reinterpret_cast<float4*>(g_aggr)[g * (DIM / 4) + lane] = acc;
#if __CUDA_ARCH__ >= 900
    cudaTriggerProgrammaticLaunchCompletion();
#endif
}

// ---------------- kernel 3: f32x2 GEMM + BN partials (PDL secondary) --------
__global__ void __launch_bounds__(256) k_gemm(const float* __restrict__ w,
                                              const float* __restrict__ b) {
    __shared__ float sA[GEMM_BM * DIM];   // sA[n_local*64 + k]
    __shared__ float sW[DIM * DIM];       // sW[k*64 + j] = w[j*64 + k]

    int tid = threadIdx.x;
    int tx = tid & 15;          // channel quad
    int ty = tid >> 4;          // node octet
    int n0 = blockIdx.x * GEMM_BM;

    for (int idx = tid; idx < DIM * DIM; idx += 256) {   // input-only: pre-sync
        int j = idx >> 6, k = idx & 63;
        sW[k * DIM + j] = w[idx];
    }
    float4 bv = *reinterpret_cast<const float4*>(&b[tx * 4]);  // input-only

#if __CUDA_ARCH__ >= 900
    cudaGridDependencySynchronize();                 // wait: g_aggr
#endif

    for (int idx = tid; idx < GEMM_BM * (DIM / 4); idx += 256) {
        int row = idx >> 4, q = idx & 15;
        int n = n0 + row;
        float4 v = (n < N_NODES)
            ? reinterpret_cast<const float4*>(g_aggr)[n * (DIM / 4) + q]
            : make_float4(0.f, 0.f, 0.f, 0.f);
        *reinterpret_cast<float4*>(&sA[row * DIM + q * 4]) = v;
    }
    __syncthreads();

    u64 acc01[8], acc23[8];
    #pragma unroll
    for (int i = 0; i < 8; i++) { acc01[i] = 0ULL; acc23[i] = 0ULL; }

    #pragma unroll 4
    for (int k = 0; k < DIM; k++) {
        double2 wp = *reinterpret_cast<const double2*>(&sW[k * DIM + tx * 4]);
        u64 w01 = __double_as_longlong(wp.x);
        u64 w23 = __double_as_longlong(wp.y);
        #pragma unroll
        for (int i = 0; i < 8; i++) {
            unsigned a = *reinterpret_cast<const unsigned*>(
                &sA[(ty * 8 + i) * DIM + k]);
            u64 aa; PACK_DUP(aa, a);
            FMA2(acc01[i], aa, w01, acc01[i]);
            FMA2(acc23[i], aa, w23, acc23[i]);
        }
    }

    float psum[4] = {0, 0, 0, 0};
    float psq[4]  = {0, 0, 0, 0};

    #pragma unroll
    for (int i = 0; i < 8; i++) {
        int n = n0 + ty * 8 + i;
        if (n < N_NODES) {
            unsigned r0, r1, r2, r3;
            UNPACK2(r0, r1, acc01[i]);
            UNPACK2(r2, r3, acc23[i]);
            float4 o;
            o.x = __uint_as_float(r0) + bv.x;
            o.y = __uint_as_float(r1) + bv.y;
            o.z = __uint_as_float(r2) + bv.z;
            o.w = __uint_as_float(r3) + bv.w;
            reinterpret_cast<float4*>(g_out)[n * (DIM / 4) + tx] = o;
            psum[0] += o.x; psum[1] += o.y; psum[2] += o.z; psum[3] += o.w;
            psq[0] += o.x * o.x; psq[1] += o.y * o.y;
            psq[2] += o.z * o.z; psq[3] += o.w * o.w;
        }
    }

    __syncthreads();
    float (*sRed)[DIM] = reinterpret_cast<float (*)[DIM]>(sA);

    #pragma unroll
    for (int c = 0; c < 4; c++) sRed[ty][tx * 4 + c] = psum[c];
    __syncthreads();
    #pragma unroll
    for (int st = 8; st > 0; st >>= 1) {
        if (ty < st)
            #pragma unroll
            for (int c = 0; c < 4; c++)
                sRed[ty][tx * 4 + c] += sRed[ty + st][tx * 4 + c];
        __syncthreads();
    }
    if (ty == 0)
        #pragma unroll
        for (int c = 0; c < 4; c++)
            atomicAdd(&g_bnstats[tx * 4 + c], sRed[0][tx * 4 + c]);
    __syncthreads();

    #pragma unroll
    for (int c = 0; c < 4; c++) sRed[ty][tx * 4 + c] = psq[c];
    __syncthreads();
    #pragma unroll
    for (int st = 8; st > 0; st >>= 1) {
        if (ty < st)
            #pragma unroll
            for (int c = 0; c < 4; c++)
                sRed[ty][tx * 4 + c] += sRed[ty + st][tx * 4 + c];
        __syncthreads();
    }
    if (ty == 0)
        #pragma unroll
        for (int c = 0; c < 4; c++)
            atomicAdd(&g_bnstats[DIM + tx * 4 + c], sRed[0][tx * 4 + c]);
#if __CUDA_ARCH__ >= 900
    cudaTriggerProgrammaticLaunchCompletion();
#endif
}

// ---------------- kernel 4: BN finalize + residual + relu (PDL secondary) ---
__global__ void k_final(const float4* __restrict__ x4,
                        const float4* __restrict__ gamma4,
                        const float4* __restrict__ beta4,
                        float4* __restrict__ out4) {
    int i = blockIdx.x * blockDim.x + threadIdx.x;
    int q = i & 15;
    bool act = (i < N_NODES * (DIM / 4));
    float4 xv = make_float4(0.f, 0.f, 0.f, 0.f);
    float4 gm = make_float4(0.f, 0.f, 0.f, 0.f);
    float4 bt = make_float4(0.f, 0.f, 0.f, 0.f);
    if (act) {
        xv = __ldg(x4 + i);
        gm = __ldg(gamma4 + q);
        bt = __ldg(beta4 + q);
    }
#if __CUDA_ARCH__ >= 900
    cudaGridDependencySynchronize();                 // wait: g_bnstats/g_out
#endif
    if (i < N_NODES) g_cnt[i] = 0;                   // reset for next launch
    if (!act) return;
    const float invN = 1.0f / (float)N_NODES;

    float4 s  = *reinterpret_cast<const float4*>(&g_bnstats[q * 4]);
    float4 sq = *reinterpret_cast<const float4*>(&g_bnstats[DIM + q * 4]);

    float m0 = s.x * invN, m1 = s.y * invN, m2 = s.z * invN, m3 = s.w * invN;
    float sc0 = gm.x * rsqrtf(sq.x * invN - m0 * m0 + BN_EPS);
    float sc1 = gm.y * rsqrtf(sq.y * invN - m1 * m1 + BN_EPS);
    float sc2 = gm.z * rsqrtf(sq.z * invN - m2 * m2 + BN_EPS);
    float sc3 = gm.w * rsqrtf(sq.w * invN - m3 * m3 + BN_EPS);
    float sh0 = bt.x - m0 * sc0;
    float sh1 = bt.y - m1 * sc1;
    float sh2 = bt.z - m2 * sc2;
    float sh3 = bt.w - m3 * sc3;

    float4 o = reinterpret_cast<const float4*>(g_out)[i];
    float4 r;
    r.x = fmaxf(fmaf(o.x, sc0, sh0) + xv.x, 0.0f);
    r.y = fmaxf(fmaf(o.y, sc1, sh1) + xv.y, 0.0f);
    r.z = fmaxf(fmaf(o.z, sc2, sh2) + xv.z, 0.0f);
    r.w = fmaxf(fmaf(o.w, sc3, sh3) + xv.w, 0.0f);
    out4[i] = r;
}

// ---------------- launch: PDL chain ------------------------------------------
template <typename... Args>
static void launch_pdl(void (*kern)(Args...), int grid, int block, bool pdl,
                       Args... args) {
    cudaLaunchConfig_t cfg = {};
    cfg.gridDim  = dim3(grid, 1, 1);
    cfg.blockDim = dim3(block, 1, 1);
    cudaLaunchAttribute attr[1];
    if (pdl) {
        attr[0].id = cudaLaunchAttributeProgrammaticStreamSerialization;
        attr[0].val.programmaticStreamSerializationAllowed = 1;
        cfg.attrs = attr;
        cfg.numAttrs = 1;
    }
    cudaLaunchKernelEx(&cfg, kern, args...);
}

extern "C" void kernel_launch(void* const* d_in, const int* in_sizes, int n_in,
                              void* d_out, int out_size) {
    const float* x     = (const float*)d_in[0];
    const int*   ei    = (const int*)d_in[1];
    const float* w     = (const float*)d_in[2];
    const float* b     = (const float*)d_in[3];
    const float* gamma = (const float*)d_in[4];
    const float* beta  = (const float*)d_in[5];
    float*       out   = (float*)d_out;

    const int vec = N_NODES * (DIM / 4);

    launch_pdl(k_scatter, (N_EDGES + 255) / 256, 256, false,
               ei, (const float2*)x);
    launch_pdl(k_aggr, (N_NODES * 16 + 255) / 256, 256, true,
               (const float4*)x);
    launch_pdl(k_gemm, GEMM_NBLK, 256, true, w, b);
    launch_pdl(k_final, (vec + 255) / 256, 256, true,
               (const float4*)x, (const float4*)gamma,
               (const float4*)beta, (float4*)out);
}